// round 12
// baseline (speedup 1.0000x reference)
#include <cuda_runtime.h>
#include <cuda_bf16.h>
#include <cstdint>

#define KTAGS 11
#define TT    2048
#define BB    4096
#define CH    8              // steps per chunk
#define NCHK  (TT / CH)      // 256
#define DEPTH 4
#define SEQ_PB 20            // 10 groups x 2 interleaved seqs (A, B)
#define FSTR  92             // floats per seq-chunk slot (368 B)
#define START_TAG 10
#define STOP_TAG  9
#define EX2C 1.4426950408889634f   // log2(e)

typedef unsigned long long u64;

__device__ __forceinline__ float ex2f(float x) {
    float r; asm("ex2.approx.f32 %0, %1;" : "=f"(r) : "f"(x)); return r;
}
__device__ __forceinline__ void kfold(float x, float& s, float& c) {
    float y = x - c;
    float t = s + y;
    c = (t - s) - y;
    s = t;
}

// cp.async with compile-time smem/gmem immediates (keeps the plan out of registers)
#define CPA(si, gi) \
    asm volatile("cp.async.ca.shared.global [%0+" #si "], [%1+" #gi "], 16;" \
                 :: "r"(sm), "l"(g))

// One gold-shifted forward step for ONE sequence of a 3-lane group.
template<bool DONORM>
__device__ __forceinline__ void crf_step(const float* __restrict__ sf, int tc, int tg,
                                         const float* __restrict__ s_trans,
                                         const float (&E)[3][9],
                                         int peer1, int peer2, int row0,
                                         float& a0, float& a1, float& a2,
                                         float& LS, float& LC, int& tagprev)
{
    const float* fr = &sf[tc * KTAGS + row0];
    float f0 = fr[0], f1 = fr[1], f2 = fr[2];
    float fg  = sf[tc * KTAGS + tg];              // group-uniform smem broadcast
    float trg = s_trans[tg * KTAGS + tagprev];    // group-uniform

    float b0 = __shfl_sync(0xffffffffu, a0, peer1);
    float b1 = __shfl_sync(0xffffffffu, a1, peer1);
    float b2 = __shfl_sync(0xffffffffu, a2, peer1);
    float c0 = __shfl_sync(0xffffffffu, a0, peer2);
    float c1 = __shfl_sync(0xffffffffu, a1, peer2);
    float c2 = __shfl_sync(0xffffffffu, a2, peer2);

    float s[3];
#pragma unroll
    for (int i = 0; i < 3; i++) {
        float t1 = E[i][0] * a0;
        t1 = fmaf(E[i][1], a1, t1);
        t1 = fmaf(E[i][2], a2, t1);
        float t2 = E[i][3] * b0;
        t2 = fmaf(E[i][4], b1, t2);
        t2 = fmaf(E[i][5], b2, t2);
        float t3 = E[i][6] * c0;
        t3 = fmaf(E[i][7], c1, t3);
        t3 = fmaf(E[i][8], c2, t3);
        s[i] = t1 + (t2 + t3);
    }

    float ndc = (-fg - trg) * EX2C;
    if (DONORM) {
        float m = fmaxf(a0, a1); m = fmaxf(m, a2);
        m = fmaxf(m, b0); m = fmaxf(m, b1); m = fmaxf(m, b2);
        m = fmaxf(m, c0); m = fmaxf(m, c1); m = fmaxf(m, c2);
        float lm = __logf(m);
        kfold(lm, LS, LC);
        ndc = fmaf(-lm, EX2C, ndc);
    }
    a0 = ex2f(fmaf(f0, EX2C, ndc)) * s[0];
    a1 = ex2f(fmaf(f1, EX2C, ndc)) * s[1];
    a2 = ex2f(fmaf(f2, EX2C, ndc)) * s[2];
    tagprev = tg;
}

// t=0 peel (gold-shifted)
__device__ __forceinline__ void crf_init(const float* __restrict__ sf, int tg0,
                                         const float* __restrict__ s_trans,
                                         const float (&SV)[3], int row0,
                                         float& a0, float& a1, float& a2, int& tagprev)
{
    float f0 = sf[row0], f1 = sf[row0 + 1], f2 = sf[row0 + 2];
    float fg  = sf[tg0];
    float tr0 = s_trans[tg0 * KTAGS + START_TAG];
    float ndc = (-fg - tr0) * EX2C;
    a0 = ex2f(fmaf(SV[0] + f0, EX2C, ndc));
    a1 = ex2f(fmaf(SV[1] + f1, EX2C, ndc));
    a2 = ex2f(fmaf(SV[2] + f2, EX2C, ndc));
    tagprev = tg0;
}

__global__ void __launch_bounds__(32, 1)
crf_nll_kernel(const float* __restrict__ feats,
               const int*   __restrict__ tags,
               const float* __restrict__ trans,
               float* __restrict__ out)
{
    __shared__ __align__(16) float s_feats[DEPTH][SEQ_PB][FSTR];  // 29440 B (slot 7360)
    __shared__ __align__(16) int   s_tags [DEPTH][SEQ_PB][CH];    //  2560 B (slot 640)
    __shared__ float s_trans[KTAGS * KTAGS];

    const int lane = threadIdx.x & 31;
    for (int i = lane; i < KTAGS * KTAGS; i += 32) s_trans[i] = trans[i];
    __syncwarp();

    // Window base: last block slides down so all 20 seqs are in range.
    int blk_base = blockIdx.x * SEQ_PB;
    if (blk_base > BB - SEQ_PB) blk_base = BB - SEQ_PB;

    // ---- affine copy plan (persistent state: gbase, sbase, 2 strides) ----
    // lanes 0..21 : unit `lane` of each seq's 352B feat chunk; seq r via immediate r*90112
    // lanes 24..31: tag units; p=lane-24 -> seq p/2 + 4q, half p%2; q via immediate q*32768
    const bool is_feat_lane = (lane < 22);
    const bool is_tag_lane  = (lane >= 24);
    u64 gbase; uint32_t sbase; uint32_t cs, ss;
    if (is_feat_lane) {
        gbase = (u64)(uintptr_t)((const char*)feats + (size_t)blk_base * TT * KTAGS * 4) + lane * 16;
        sbase = (uint32_t)__cvta_generic_to_shared(&s_feats[0][0][0]) + lane * 16;
        cs = CH * KTAGS * 4;          // 352
        ss = (uint32_t)sizeof(s_feats[0]);   // 7360
    } else {
        int p = lane - 24;              // 0..7 (only meaningful for tag lanes)
        if (p < 0) p = 0;
        gbase = (u64)(uintptr_t)((const char*)tags + (size_t)(blk_base + (p >> 1)) * TT * 4) + (p & 1) * 16;
        sbase = (uint32_t)__cvta_generic_to_shared(&s_tags[0][0][0]) + (p >> 1) * 32 + (p & 1) * 16;
        cs = CH * 4;                  // 32
        ss = (uint32_t)sizeof(s_tags[0]);    // 640
    }

    auto issue_chunk = [&](int c) {
        const int d = c & (DEPTH - 1);
        u64      g  = gbase + (u64)c * cs;
        uint32_t sm = sbase + d * ss;
        if (is_feat_lane) {
            CPA(0,     0);       CPA(368,  90112);   CPA(736,  180224);  CPA(1104, 270336);
            CPA(1472,  360448);  CPA(1840, 450560);  CPA(2208, 540672);  CPA(2576, 630784);
            CPA(2944,  720896);  CPA(3312, 811008);  CPA(3680, 901120);  CPA(4048, 991232);
            CPA(4416, 1081344);  CPA(4784, 1171456); CPA(5152, 1261568); CPA(5520, 1351680);
            CPA(5888, 1441792);  CPA(6256, 1531904); CPA(6624, 1622016); CPA(6992, 1712128);
        } else if (is_tag_lane) {
            CPA(0, 0); CPA(128, 32768); CPA(256, 65536); CPA(384, 98304); CPA(512, 131072);
        }
        asm volatile("cp.async.commit_group;" ::: "memory");
    };

    // lane -> (group, k); lanes 30,31 shadow group 0 k=0,1 (results discarded)
    int grp, k;
    if (lane < 30) { grp = lane / 3; k = lane - 3 * grp; }
    else           { grp = 0;        k = lane - 30;      }
    const int glane = 3 * grp;
    const int k1 = (k + 1) % 3, k2 = (k + 2) % 3;
    const int peer1 = glane + k1, peer2 = glane + k2;
    const int row0 = 3 * k;
    const int bA = blk_base + grp;        // < BB
    const int bB = bA + 10;               // < BB (window slid)

    // E shared between A and B scans; columns permuted to gather order
    float E[3][9], SV[3], ES[3];
#pragma unroll
    for (int i = 0; i < 3; i++) {
        const float* tr = &s_trans[(row0 + i) * KTAGS];
#pragma unroll
        for (int q = 0; q < 3; q++) {
            E[i][q]     = __expf(tr[3 * k  + q]);
            E[i][3 + q] = __expf(tr[3 * k1 + q]);
            E[i][6 + q] = __expf(tr[3 * k2 + q]);
        }
        SV[i] = tr[START_TAG];
        ES[i] = __expf(s_trans[STOP_TAG * KTAGS + (row0 + i)]);
    }

#pragma unroll
    for (int c = 0; c < DEPTH; c++) issue_chunk(c);

    // Two independent scans per group (ILP partner for the serial chain)
    float aA0 = 0.f, aA1 = 0.f, aA2 = 0.f, LSA = 0.f, LCA = 0.f;
    float aB0 = 0.f, aB1 = 0.f, aB2 = 0.f, LSB = 0.f, LCB = 0.f;
    int   tpA = START_TAG, tpB = START_TAG;

    for (int c = 0; c < NCHK; c++) {
        asm volatile("cp.async.wait_group %0;" :: "n"(DEPTH - 1) : "memory");
        __syncwarp();

        const int d = c & (DEPTH - 1);
        const float* sfA = &s_feats[d][grp][0];
        const float* sfB = &s_feats[d][10 + grp][0];
        const int4*  tqA = (const int4*)&s_tags[d][grp][0];
        const int4*  tqB = (const int4*)&s_tags[d][10 + grp][0];
        int4 tA0 = tqA[0], tA1 = tqA[1];
        int4 tB0 = tqB[0], tB1 = tqB[1];
        int tgsA[8] = {tA0.x, tA0.y, tA0.z, tA0.w, tA1.x, tA1.y, tA1.z, tA1.w};
        int tgsB[8] = {tB0.x, tB0.y, tB0.z, tB0.w, tB1.x, tB1.y, tB1.z, tB1.w};

        if (c == 0) {
            crf_init(sfA, tgsA[0], s_trans, SV, row0, aA0, aA1, aA2, tpA);
            crf_init(sfB, tgsB[0], s_trans, SV, row0, aB0, aB1, aB2, tpB);
#pragma unroll
            for (int tc = 1; tc < CH; tc++) {
                crf_step<false>(sfA, tc, tgsA[tc], s_trans, E, peer1, peer2, row0,
                                aA0, aA1, aA2, LSA, LCA, tpA);
                crf_step<false>(sfB, tc, tgsB[tc], s_trans, E, peer1, peer2, row0,
                                aB0, aB1, aB2, LSB, LCB, tpB);
            }
        } else {
            crf_step<true>(sfA, 0, tgsA[0], s_trans, E, peer1, peer2, row0,
                           aA0, aA1, aA2, LSA, LCA, tpA);
            crf_step<true>(sfB, 0, tgsB[0], s_trans, E, peer1, peer2, row0,
                           aB0, aB1, aB2, LSB, LCB, tpB);
#pragma unroll
            for (int tc = 1; tc < CH; tc++) {
                crf_step<false>(sfA, tc, tgsA[tc], s_trans, E, peer1, peer2, row0,
                                aA0, aA1, aA2, LSA, LCA, tpA);
                crf_step<false>(sfB, tc, tgsB[tc], s_trans, E, peer1, peer2, row0,
                                aB0, aB1, aB2, LSB, LCB, tpB);
            }
        }

        __syncwarp();
        if (c + DEPTH < NCHK) issue_chunk(c + DEPTH);
        else asm volatile("cp.async.commit_group;" ::: "memory");
    }

    // finalize both: NLL = L + log(sum_p a_p e^{trans[STOP,p]}) - trans[STOP, tag_last]
    float termA = aA0 * ES[0];
    termA = fmaf(aA1, ES[1], termA);
    termA = fmaf(aA2, ES[2], termA);
    float fsumA = termA + __shfl_sync(0xffffffffu, termA, peer1)
                        + __shfl_sync(0xffffffffu, termA, peer2);
    float termB = aB0 * ES[0];
    termB = fmaf(aB1, ES[1], termB);
    termB = fmaf(aB2, ES[2], termB);
    float fsumB = termB + __shfl_sync(0xffffffffu, termB, peer1)
                        + __shfl_sync(0xffffffffu, termB, peer2);

    float resA = (LSA - LCA) + __logf(fsumA) - s_trans[STOP_TAG * KTAGS + tpA];
    float resB = (LSB - LCB) + __logf(fsumB) - s_trans[STOP_TAG * KTAGS + tpB];

    if (lane < 30 && k == 0) {
        out[bA] = resA;
        out[bB] = resB;
    }
}

extern "C" void kernel_launch(void* const* d_in, const int* in_sizes, int n_in,
                              void* d_out, int out_size)
{
    const float* feats = (const float*)d_in[0];
    const int*   tags  = (const int*)d_in[1];
    const float* trans = (const float*)d_in[2];
    float* out = (float*)d_out;

    dim3 grid((BB + SEQ_PB - 1) / SEQ_PB);   // 205 single-warp blocks
    dim3 block(32);
    crf_nll_kernel<<<grid, block>>>(feats, tags, trans, out);
}

// round 13
// speedup vs baseline: 1.9438x; 1.9438x over previous
#include <cuda_runtime.h>
#include <cuda_bf16.h>
#include <cstdint>

#define KTAGS 11
#define TT    2048
#define BB    4096
#define CH    8              // steps per chunk
#define NCHK  (TT / CH)      // 256
#define DEPTH 4
#define WARPS_PB 3
#define SEQ_PW   10
#define SEQ_PB   (WARPS_PB * SEQ_PW)   // 30
#define THREADS  (WARPS_PB * 32)       // 96
#define FSTRIDE  92
#define START_TAG 10
#define STOP_TAG  9
#define EX2C 1.4426950408889634f   // log2(e)

__device__ __forceinline__ float ex2f(float x) {
    float r; asm("ex2.approx.f32 %0, %1;" : "=f"(r) : "f"(x)); return r;
}
__device__ __forceinline__ void kfold(float x, float& s, float& c) {
    float y = x - c;
    float t = s + y;
    c = (t - s) - y;
    s = t;
}

// One gold-shifted forward step. Single-chain dots (own states head the chain
// so the first links overlap the shuffle latency).
template<bool DONORM>
__device__ __forceinline__ void crf_step(const float* __restrict__ sf, int tc, int tg,
                                         const float* __restrict__ s_trans,
                                         const float (&E)[3][9],
                                         int peer1, int peer2, int row0,
                                         float& a0, float& a1, float& a2,
                                         float& LS, float& LC, int& tagprev)
{
    const float* fr = &sf[tc * KTAGS + row0];
    float f0 = fr[0], f1 = fr[1], f2 = fr[2];
    float fg  = sf[tc * KTAGS + tg];              // group-uniform smem broadcast
    float trg = s_trans[tg * KTAGS + tagprev];    // group-uniform

    float b0 = __shfl_sync(0xffffffffu, a0, peer1);
    float b1 = __shfl_sync(0xffffffffu, a1, peer1);
    float b2 = __shfl_sync(0xffffffffu, a2, peer1);
    float c0 = __shfl_sync(0xffffffffu, a0, peer2);
    float c1 = __shfl_sync(0xffffffffu, a1, peer2);
    float c2 = __shfl_sync(0xffffffffu, a2, peer2);

    float s0 = E[0][0] * a0;
    s0 = fmaf(E[0][1], a1, s0); s0 = fmaf(E[0][2], a2, s0);
    s0 = fmaf(E[0][3], b0, s0); s0 = fmaf(E[0][4], b1, s0); s0 = fmaf(E[0][5], b2, s0);
    s0 = fmaf(E[0][6], c0, s0); s0 = fmaf(E[0][7], c1, s0); s0 = fmaf(E[0][8], c2, s0);
    float s1 = E[1][0] * a0;
    s1 = fmaf(E[1][1], a1, s1); s1 = fmaf(E[1][2], a2, s1);
    s1 = fmaf(E[1][3], b0, s1); s1 = fmaf(E[1][4], b1, s1); s1 = fmaf(E[1][5], b2, s1);
    s1 = fmaf(E[1][6], c0, s1); s1 = fmaf(E[1][7], c1, s1); s1 = fmaf(E[1][8], c2, s1);
    float s2 = E[2][0] * a0;
    s2 = fmaf(E[2][1], a1, s2); s2 = fmaf(E[2][2], a2, s2);
    s2 = fmaf(E[2][3], b0, s2); s2 = fmaf(E[2][4], b1, s2); s2 = fmaf(E[2][5], b2, s2);
    s2 = fmaf(E[2][6], c0, s2); s2 = fmaf(E[2][7], c1, s2); s2 = fmaf(E[2][8], c2, s2);

    float ndc = (-fg - trg) * EX2C;
    if (DONORM) {
        float m = fmaxf(a0, a1); m = fmaxf(m, a2);
        m = fmaxf(m, b0); m = fmaxf(m, b1); m = fmaxf(m, b2);
        m = fmaxf(m, c0); m = fmaxf(m, c1); m = fmaxf(m, c2);
        float lm = __logf(m);
        kfold(lm, LS, LC);
        ndc = fmaf(-lm, EX2C, ndc);
    }
    a0 = ex2f(fmaf(f0, EX2C, ndc)) * s0;
    a1 = ex2f(fmaf(f1, EX2C, ndc)) * s1;
    a2 = ex2f(fmaf(f2, EX2C, ndc)) * s2;
    tagprev = tg;
}

__global__ void __launch_bounds__(THREADS, 1)
crf_nll_kernel(const float* __restrict__ feats,
               const int*   __restrict__ tags,
               const float* __restrict__ trans,
               float* __restrict__ out)
{
    __shared__ __align__(16) float s_feats[DEPTH][WARPS_PB][SEQ_PW][FSTRIDE]; // 44160 B
    __shared__ __align__(16) int   s_tags [DEPTH][WARPS_PB][SEQ_PW][CH];      //  3840 B
    __shared__ float s_trans[KTAGS * KTAGS];

    const int tid = threadIdx.x;
    if (tid < KTAGS * KTAGS) s_trans[tid] = trans[tid];
    __syncthreads();

    const int w    = tid >> 5;
    const int lane = tid & 31;
    int grp, k;
    if (lane < 30) { grp = lane / 3; k = lane - 3 * grp; }
    else           { grp = 0;        k = lane - 30;      }
    const int glane = 3 * grp;
    const int k1 = (k + 1) % 3, k2 = (k + 2) % 3;
    const int peer1 = glane + k1, peer2 = glane + k2;
    const int row0 = 3 * k;
    const int b = blockIdx.x * SEQ_PB + w * SEQ_PW + grp;
    const bool writer = (lane < 30) && (k == 0) && (b < BB);

    float E[3][9], SV[3], ES[3];
#pragma unroll
    for (int i = 0; i < 3; i++) {
        const float* tr = &s_trans[(row0 + i) * KTAGS];
#pragma unroll
        for (int q = 0; q < 3; q++) {
            E[i][q]     = __expf(tr[3 * k  + q]);
            E[i][3 + q] = __expf(tr[3 * k1 + q]);
            E[i][6 + q] = __expf(tr[3 * k2 + q]);
        }
        SV[i] = tr[START_TAG];
        ES[i] = __expf(s_trans[STOP_TAG * KTAGS + (row0 + i)]);
    }

    // ---- cp.async plan (R2/R9-proven): 240 16B units spread over all 32 lanes ----
    const char* srcp[8];
    uint32_t    dstp[8];
    int         sadv[8];
    int         dadv[8];
    bool        act [8];
#pragma unroll
    for (int r = 0; r < 8; r++) {
        int u = lane + 32 * r;
        act[r] = (u < 240);
        int uu = act[r] ? u : 0;
        int s  = uu / 24;
        int kk = uu % 24;
        int bs = blockIdx.x * SEQ_PB + w * SEQ_PW + s;
        if (bs >= BB) bs = BB - 1;
        if (kk < 22) {
            srcp[r] = (const char*)feats + (size_t)bs * TT * KTAGS * 4 + kk * 16;
            sadv[r] = CH * KTAGS * 4;
            dstp[r] = (uint32_t)__cvta_generic_to_shared(&s_feats[0][w][s][kk * 4]);
            dadv[r] = (int)sizeof(s_feats[0]);
        } else {
            srcp[r] = (const char*)tags + (size_t)bs * TT * 4 + (kk - 22) * 16;
            sadv[r] = CH * 4;
            dstp[r] = (uint32_t)__cvta_generic_to_shared(&s_tags[0][w][s][(kk - 22) * 4]);
            dadv[r] = (int)sizeof(s_tags[0]);
        }
    }

    auto issue_chunk = [&](int c) {
        int d = c & (DEPTH - 1);
#pragma unroll
        for (int r = 0; r < 8; r++) {
            if (act[r]) {
                uint32_t dd = dstp[r] + d * dadv[r];
                const char* ss = srcp[r] + (size_t)c * sadv[r];
                asm volatile("cp.async.ca.shared.global [%0], [%1], 16;" :: "r"(dd), "l"(ss));
            }
        }
        asm volatile("cp.async.commit_group;" ::: "memory");
    };

#pragma unroll
    for (int c = 0; c < DEPTH; c++) issue_chunk(c);

    float a0 = 0.f, a1 = 0.f, a2 = 0.f;
    float LS = 0.f, LC = 0.f;
    int   tagprev = START_TAG;

    // Process one 8-step slot. FIRSTNORM: norm at tc=0 (false only for chunk 0).
    auto do8 = [&](int d, bool c0peel) {
        const float* sf = &s_feats[d][w][grp][0];
        const int4*  tq = (const int4*)&s_tags[d][w][grp][0];
        int4 tA = tq[0], tB = tq[1];
        int tgs[8] = {tA.x, tA.y, tA.z, tA.w, tB.x, tB.y, tB.z, tB.w};

        if (c0peel) {
            float f0 = sf[row0], f1 = sf[row0 + 1], f2 = sf[row0 + 2];
            int tg0 = tgs[0];
            float fg  = sf[tg0];
            float tr0 = s_trans[tg0 * KTAGS + START_TAG];
            float ndc = (-fg - tr0) * EX2C;
            a0 = ex2f(fmaf(SV[0] + f0, EX2C, ndc));
            a1 = ex2f(fmaf(SV[1] + f1, EX2C, ndc));
            a2 = ex2f(fmaf(SV[2] + f2, EX2C, ndc));
            tagprev = tg0;
        } else {
            crf_step<true>(sf, 0, tgs[0], s_trans, E, peer1, peer2, row0,
                           a0, a1, a2, LS, LC, tagprev);
        }
#pragma unroll
        for (int tc = 1; tc < CH; tc++)
            crf_step<false>(sf, tc, tgs[tc], s_trans, E, peer1, peer2, row0,
                            a0, a1, a2, LS, LC, tagprev);
    };

    // Paired-chunk loop: one wait + one sync pair per 16 steps.
    for (int c = 0; c < NCHK; c += 2) {
        asm volatile("cp.async.wait_group %0;" :: "n"(DEPTH - 2) : "memory");
        __syncwarp();

        do8(c & (DEPTH - 1), c == 0);
        do8((c + 1) & (DEPTH - 1), false);

        __syncwarp();
        if (c + DEPTH < NCHK) {
            issue_chunk(c + DEPTH);
            issue_chunk(c + DEPTH + 1);
        } else {
            asm volatile("cp.async.commit_group;" ::: "memory");
            asm volatile("cp.async.commit_group;" ::: "memory");
        }
    }

    // finalize: NLL = L + log( sum_p a_p * exp(trans[STOP,p]) ) - trans[STOP, tag_last]
    float term = a0 * ES[0];
    term = fmaf(a1, ES[1], term);
    term = fmaf(a2, ES[2], term);
    float fsum = term + __shfl_sync(0xffffffffu, term, peer1)
                      + __shfl_sync(0xffffffffu, term, peer2);

    float res = (LS - LC) + __logf(fsum) - s_trans[STOP_TAG * KTAGS + tagprev];

    if (writer) out[b] = res;
}

extern "C" void kernel_launch(void* const* d_in, const int* in_sizes, int n_in,
                              void* d_out, int out_size)
{
    const float* feats = (const float*)d_in[0];
    const int*   tags  = (const int*)d_in[1];
    const float* trans = (const float*)d_in[2];
    float* out = (float*)d_out;

    dim3 grid((BB + SEQ_PB - 1) / SEQ_PB);   // 137 blocks, single wave
    dim3 block(THREADS);                     // 96 threads = 3 warps = 30 sequences
    crf_nll_kernel<<<grid, block>>>(feats, tags, trans, out);
}